// round 2
// baseline (speedup 1.0000x reference)
#include <cuda_runtime.h>
#include <math.h>

#define B 16
#define CIN 512
#define COUT 512
#define HH 64
#define WW 64
#define KK 3
#define SS 512

// scale = 1/sqrt(Cin*K*K) = 1/sqrt(4608)
#define SCALE2 (1.0f / 4608.0f)

// Scratch (allocation-free rule: __device__ globals)
__device__ float g_s[B * CIN];          // modulation scales s[b][ci]
__device__ float g_demod[B * COUT];     // demod[b][co]
__device__ float g_wsq[COUT * CIN];     // sum_k weight^2 [co][ci]
__device__ float g_wt[CIN * COUT * 9];  // weight transposed to [ci][co][k]

// ---------------------------------------------------------------------------
// Kernel 1: s[b][ci] = style[b,:] . mod_w[ci,:] + mod_b[ci]
// grid (16, 64), block 256 (8 warps); warp handles one ci row
// ---------------------------------------------------------------------------
__global__ void k_style(const float* __restrict__ style,
                        const float* __restrict__ mod_w,
                        const float* __restrict__ mod_b) {
    __shared__ float ss[SS];
    const int b = blockIdx.x;
    const int lane = threadIdx.x & 31;
    const int warp = threadIdx.x >> 5;
    const int ci = blockIdx.y * 8 + warp;

    for (int i = threadIdx.x; i < SS; i += 256) ss[i] = style[b * SS + i];
    __syncthreads();

    const float* wr = mod_w + (size_t)ci * SS;
    float p = 0.f;
    #pragma unroll 4
    for (int j = lane; j < SS; j += 32) p = fmaf(wr[j], ss[j], p);
    #pragma unroll
    for (int o = 16; o > 0; o >>= 1) p += __shfl_xor_sync(0xffffffffu, p, o);
    if (lane == 0) g_s[b * CIN + ci] = p + mod_b[ci];
}

// ---------------------------------------------------------------------------
// Kernel 2: wsq[co][ci] = sum_k weight[co][ci][k]^2
// ---------------------------------------------------------------------------
__global__ void k_wsq(const float* __restrict__ weight) {
    int idx = blockIdx.x * blockDim.x + threadIdx.x;
    if (idx >= COUT * CIN) return;
    const float* w = weight + (size_t)idx * 9;
    float s = 0.f;
    #pragma unroll
    for (int k = 0; k < 9; k++) s = fmaf(w[k], w[k], s);
    g_wsq[idx] = s;
}

// ---------------------------------------------------------------------------
// Kernel 3: transpose weight [co][ci][9] -> [ci][co][9] (coalesced writes)
// ---------------------------------------------------------------------------
__global__ void k_wt(const float* __restrict__ weight) {
    int t = blockIdx.x * blockDim.x + threadIdx.x;
    if (t >= CIN * COUT * 9) return;
    int k = t % 9;
    int co = (t / 9) & (COUT - 1);
    int ci = t / (9 * COUT);
    g_wt[t] = weight[((size_t)co * CIN + ci) * 9 + k];
}

// ---------------------------------------------------------------------------
// Kernel 4: demod[b][co] = rsqrt( SCALE2 * sum_ci wsq[co][ci]*s[b][ci]^2 + 1e-8 )
// one warp per (b,co); grid 1024 x 256 threads = 8192 warps
// ---------------------------------------------------------------------------
__global__ void k_demod() {
    int wid = (blockIdx.x * blockDim.x + threadIdx.x) >> 5;
    int lane = threadIdx.x & 31;
    int b = wid >> 9;          // /512
    int co = wid & 511;
    const float* wsq = g_wsq + (size_t)co * CIN;
    const float* sr = g_s + (size_t)b * CIN;
    float p = 0.f;
    #pragma unroll 4
    for (int j = lane; j < CIN; j += 32) {
        float sv = sr[j];
        p = fmaf(wsq[j], sv * sv, p);
    }
    #pragma unroll
    for (int o = 16; o > 0; o >>= 1) p += __shfl_xor_sync(0xffffffffu, p, o);
    if (lane == 0) g_demod[b * COUT + co] = rsqrtf(SCALE2 * p + 1e-8f);
}

// ---------------------------------------------------------------------------
// Kernel 5: batch-shared 3x3 conv with s folded into input loads and
// scale*demod folded into the epilogue.
// Tile: 64 cout x (8 rows x 32 cols). 256 threads.
//  - lane (tid&31)  -> output column
//  - warp (tid>>5)  -> 8 couts (warp*8 .. warp*8+7)
//  - each thread: 8 couts x 8 rows = 64 fp32 accumulators
// grid: (2 x-tiles, 8 y-tiles, 128 = b*8 + co_tile)
// ---------------------------------------------------------------------------
__global__ void __launch_bounds__(256)
k_conv(const float* __restrict__ input, float* __restrict__ out) {
    __shared__ float s_in[10][36];   // (8+2) x (32+2) halo tile, padded
    __shared__ float s_w[64 * 9];    // weights for 64 couts at current ci
    __shared__ float s_s[CIN];       // s[b][:]

    const int tx = threadIdx.x & 31;
    const int warp = threadIdx.x >> 5;
    const int x0 = blockIdx.x * 32;
    const int y0 = blockIdx.y * 8;
    const int bz = blockIdx.z;
    const int b = bz >> 3;
    const int co0 = (bz & 7) * 64;

    for (int i = threadIdx.x; i < CIN; i += 256) s_s[i] = g_s[b * CIN + i];
    __syncthreads();

    float acc[8][8];
    #pragma unroll
    for (int c = 0; c < 8; c++)
        #pragma unroll
        for (int r = 0; r < 8; r++) acc[c][r] = 0.f;

    const float* in_b = input + (size_t)b * CIN * (HH * WW);

    for (int ci = 0; ci < CIN; ci++) {
        // --- stage input tile (x modulation scale s) ---
        const float sval = s_s[ci];
        const float* inp = in_b + (size_t)ci * (HH * WW);
        #pragma unroll
        for (int i = threadIdx.x; i < 340; i += 256) {
            int r = i / 34, c = i % 34;
            int gy = y0 - 1 + r, gx = x0 - 1 + c;
            float v = 0.f;
            if (gy >= 0 && gy < HH && gx >= 0 && gx < WW) v = inp[gy * WW + gx];
            s_in[r][c] = v * sval;
        }
        // --- stage weights for this ci (coalesced from transposed layout) ---
        const float* wp = g_wt + (size_t)ci * (COUT * 9) + (size_t)co0 * 9;
        #pragma unroll
        for (int i = threadIdx.x; i < 576; i += 256) s_w[i] = wp[i];
        __syncthreads();

        // --- register-load the 3 input columns this thread needs ---
        float in_reg[10][3];
        #pragma unroll
        for (int r = 0; r < 10; r++) {
            in_reg[r][0] = s_in[r][tx];
            in_reg[r][1] = s_in[r][tx + 1];
            in_reg[r][2] = s_in[r][tx + 2];
        }

        // --- 8 couts x 8 rows x 9 taps ---
        #pragma unroll
        for (int c = 0; c < 8; c++) {
            const float* w = &s_w[(warp * 8 + c) * 9];
            const float w00 = w[0], w01 = w[1], w02 = w[2];
            const float w10 = w[3], w11 = w[4], w12 = w[5];
            const float w20 = w[6], w21 = w[7], w22 = w[8];
            #pragma unroll
            for (int r = 0; r < 8; r++) {
                float a = acc[c][r];
                a = fmaf(w00, in_reg[r][0], a);
                a = fmaf(w01, in_reg[r][1], a);
                a = fmaf(w02, in_reg[r][2], a);
                a = fmaf(w10, in_reg[r + 1][0], a);
                a = fmaf(w11, in_reg[r + 1][1], a);
                a = fmaf(w12, in_reg[r + 1][2], a);
                a = fmaf(w20, in_reg[r + 2][0], a);
                a = fmaf(w21, in_reg[r + 2][1], a);
                a = fmaf(w22, in_reg[r + 2][2], a);
                acc[c][r] = a;
            }
        }
        __syncthreads();
    }

    // --- epilogue: multiply by scale * demod[b][co], store ---
    const float scale = rsqrtf(4608.0f);
    #pragma unroll
    for (int c = 0; c < 8; c++) {
        const int co = co0 + warp * 8 + c;
        const float f = g_demod[b * COUT + co] * scale;
        #pragma unroll
        for (int r = 0; r < 8; r++) {
            out[(((size_t)b * COUT + co) * HH + (y0 + r)) * WW + (x0 + tx)] =
                acc[c][r] * f;
        }
    }
}

// ---------------------------------------------------------------------------
extern "C" void kernel_launch(void* const* d_in, const int* in_sizes, int n_in,
                              void* d_out, int out_size) {
    const float* input  = (const float*)d_in[0];   // (16,512,64,64)
    const float* style  = (const float*)d_in[1];   // (16,512)
    const float* weight = (const float*)d_in[2];   // (512,512,3,3)
    const float* mod_w  = (const float*)d_in[3];   // (512,512)
    const float* mod_b  = (const float*)d_in[4];   // (512)
    float* out = (float*)d_out;                    // (16,512,64,64)

    k_style<<<dim3(16, 64), 256>>>(style, mod_w, mod_b);
    k_wsq<<<(COUT * CIN + 255) / 256, 256>>>(weight);
    k_wt<<<(CIN * COUT * 9 + 255) / 256, 256>>>(weight);
    k_demod<<<1024, 256>>>();
    k_conv<<<dim3(2, 8, 128), 256>>>(input, out);
}

// round 3
// speedup vs baseline: 5.7734x; 5.7734x over previous
#include <cuda_runtime.h>
#include <math.h>
#include <stdint.h>

#define B 16
#define CIN 512
#define COUT 512
#define HH 64
#define WW 64
#define SS 512

#define SCALE2 (1.0f / 4608.0f)

// ---------------- scratch (__device__ globals; no runtime alloc) ------------
__device__ float    g_s[B * CIN];            // modulation s[b][ci]
__device__ float    g_demod[B * COUT];       // demod[b][co]
__device__ float    g_wsq[COUT * CIN];       // sum_k weight^2
// weights in per-thread A-fragment order (tf32 bits):
// layout [mt(4)][kstep(64)][tap(9)][wm(2)*512 + im(4)*128 + lane(32)*4 + j(4)]
__device__ uint32_t g_wf[4 * 64 * 9 * 1024];

// ---------------------------------------------------------------------------
__global__ void k_style(const float* __restrict__ style,
                        const float* __restrict__ mod_w,
                        const float* __restrict__ mod_b) {
    __shared__ float ss[SS];
    const int b = blockIdx.x;
    const int lane = threadIdx.x & 31;
    const int warp = threadIdx.x >> 5;
    const int ci = blockIdx.y * 8 + warp;
    for (int i = threadIdx.x; i < SS; i += 256) ss[i] = style[b * SS + i];
    __syncthreads();
    const float* wr = mod_w + (size_t)ci * SS;
    float p = 0.f;
    #pragma unroll 4
    for (int j = lane; j < SS; j += 32) p = fmaf(wr[j], ss[j], p);
    #pragma unroll
    for (int o = 16; o > 0; o >>= 1) p += __shfl_xor_sync(0xffffffffu, p, o);
    if (lane == 0) g_s[b * CIN + ci] = p + mod_b[ci];
}

__global__ void k_wsq(const float* __restrict__ weight) {
    int idx = blockIdx.x * blockDim.x + threadIdx.x;
    if (idx >= COUT * CIN) return;
    const float* w = weight + (size_t)idx * 9;
    float s = 0.f;
    #pragma unroll
    for (int k = 0; k < 9; k++) s = fmaf(w[k], w[k], s);
    g_wsq[idx] = s;
}

__global__ void k_demod() {
    int wid = (blockIdx.x * blockDim.x + threadIdx.x) >> 5;
    int lane = threadIdx.x & 31;
    int b = wid >> 9;
    int co = wid & 511;
    const float* wsq = g_wsq + (size_t)co * CIN;
    const float* sr = g_s + (size_t)b * CIN;
    float p = 0.f;
    #pragma unroll 4
    for (int j = lane; j < CIN; j += 32) {
        float sv = sr[j];
        p = fmaf(wsq[j], sv * sv, p);
    }
    #pragma unroll
    for (int o = 16; o > 0; o >>= 1) p += __shfl_xor_sync(0xffffffffu, p, o);
    if (lane == 0) g_demod[b * COUT + co] = rsqrtf(SCALE2 * p + 1e-8f);
}

// ---------------------------------------------------------------------------
// Weight -> fragment-major tf32 layout.
// a0:(m,k) a1:(m+8,k) a2:(m,k+4) a3:(m+8,k+4) per PTX m16n8k8.tf32 A mapping.
// ---------------------------------------------------------------------------
__global__ void k_wf(const float* __restrict__ weight) {
    int idx = blockIdx.x * blockDim.x + threadIdx.x;
    if (idx >= 4 * 64 * 9 * 1024) return;
    int j    = idx & 3;
    int lane = (idx >> 2) & 31;
    int im   = (idx >> 7) & 3;
    int wm   = (idx >> 9) & 1;
    int rest = idx >> 10;         // tap + 9*(kstep + 64*mt)
    int t    = rest % 9;
    int r2   = rest / 9;
    int s_   = r2 & 63;
    int mt   = r2 >> 6;
    int co = mt * 128 + wm * 64 + im * 16 + (lane >> 2) + (j & 1) * 8;
    int ci = s_ * 8 + (lane & 3) + (j >> 1) * 4;
    float v = weight[((size_t)co * CIN + ci) * 9 + t];
    uint32_t o;
    asm("cvt.rna.tf32.f32 %0, %1;" : "=r"(o) : "f"(v));
    g_wf[idx] = o;
}

// ---------------------------------------------------------------------------
// Conv as TF32 implicit GEMM.
// CTA: 128 co x 128 px (2 output rows x 64 cols), 256 threads (8 warps).
// Warp tile 32(co) x 32(px): warps arranged wm(2) x wn(4); wn -> (row, xhalf).
// ci chunked by 16 (2 k-steps of 8); 9 taps via shifted reads of halo tile.
// ---------------------------------------------------------------------------
#define NCHUNK 32
#define SW_WORDS (2 * 9 * 1024)        // 18432
#define SIN_WORDS (16 * 4 * 66)        // 4224

#define MMA_TF32(d, a, b0v, b1v)                                              \
    asm volatile(                                                             \
        "mma.sync.aligned.m16n8k8.row.col.f32.tf32.tf32.f32 "                 \
        "{%0,%1,%2,%3}, {%4,%5,%6,%7}, {%8,%9}, {%0,%1,%2,%3};"               \
        : "+f"(d[0]), "+f"(d[1]), "+f"(d[2]), "+f"(d[3])                      \
        : "r"(a.x), "r"(a.y), "r"(a.z), "r"(a.w), "r"(b0v), "r"(b1v))

__global__ void __launch_bounds__(256, 2)
k_conv(const float* __restrict__ input, float* __restrict__ out) {
    extern __shared__ uint32_t smem[];
    uint32_t* s_w  = smem;              // [ks][tap][1024]
    uint32_t* s_in = smem + SW_WORDS;   // [ci(16)][r(4)][66]

    const int tid  = threadIdx.x;
    const int lane = tid & 31;
    const int wid  = tid >> 5;
    const int wm = wid >> 2;
    const int wn = wid & 3;
    const int yl = wn >> 1;
    const int xw = (wn & 1) * 32;
    const int g  = lane >> 2;      // groupID
    const int tt = lane & 3;       // threadID in group

    const int mt = blockIdx.x;
    const int y0 = blockIdx.y * 2;
    const int b  = blockIdx.z;
    const int co0 = mt * 128;

    float acc[4][4][4];
    #pragma unroll
    for (int a = 0; a < 4; a++)
        #pragma unroll
        for (int n = 0; n < 4; n++)
            #pragma unroll
            for (int c = 0; c < 4; c++) acc[a][n][c] = 0.f;

    const float* in_b = input + (size_t)b * CIN * (HH * WW);
    const float* s_b  = g_s + b * CIN;

    for (int chunk = 0; chunk < NCHUNK; chunk++) {
        const int ci0 = chunk * 16;
        // ---- stage weights: contiguous copy of fragment-major slab ----
        {
            const uint4* src = (const uint4*)(g_wf + ((size_t)(mt * 64 + chunk * 2) * 9) * 1024);
            uint4* dst = (uint4*)s_w;
            #pragma unroll 4
            for (int i = tid; i < SW_WORDS / 4; i += 256) dst[i] = src[i];
        }
        // ---- stage input tile (modulated, tf32-rounded), with halo ----
        #pragma unroll 4
        for (int i = tid; i < SIN_WORDS; i += 256) {
            int ci  = i / 264;
            int rem = i - ci * 264;
            int r   = rem / 66;
            int c   = rem - r * 66;
            int gy = y0 - 1 + r;
            int gx = c - 1;
            float v = 0.f;
            if (gy >= 0 && gy < HH && gx >= 0 && gx < WW)
                v = in_b[(((size_t)(ci0 + ci)) << 12) + (gy << 6) + gx] * s_b[ci0 + ci];
            uint32_t o;
            asm("cvt.rna.tf32.f32 %0, %1;" : "=r"(o) : "f"(v));
            s_in[i] = o;
        }
        __syncthreads();

        // ---- compute: 9 taps x 2 k-steps ----
        #pragma unroll
        for (int t = 0; t < 9; t++) {
            const int dy = t / 3, dx = t % 3;
            const int r = yl + dy;
            #pragma unroll
            for (int ks = 0; ks < 2; ks++) {
                const uint32_t* wp = s_w + (ks * 9 + t) * 1024 + wm * 512 + lane * 4;
                uint4 A0 = *(const uint4*)(wp);
                uint4 A1 = *(const uint4*)(wp + 128);
                uint4 A2 = *(const uint4*)(wp + 256);
                uint4 A3 = *(const uint4*)(wp + 384);
                const uint32_t* bp = s_in + (ks * 8 + tt) * 264 + r * 66 + xw + dx + g;
                #pragma unroll
                for (int nf = 0; nf < 4; nf++) {
                    uint32_t b0 = bp[nf * 8];
                    uint32_t b1 = bp[nf * 8 + 4 * 264];
                    MMA_TF32(acc[0][nf], A0, b0, b1);
                    MMA_TF32(acc[1][nf], A1, b0, b1);
                    MMA_TF32(acc[2][nf], A2, b0, b1);
                    MMA_TF32(acc[3][nf], A3, b0, b1);
                }
            }
        }
        __syncthreads();
    }

    // ---- epilogue: scale * demod, write ----
    const float scale = rsqrtf(4608.0f);
    const int y = y0 + yl;
    #pragma unroll
    for (int im = 0; im < 4; im++) {
        const int coA = co0 + wm * 64 + im * 16 + g;
        const float fA = g_demod[b * COUT + coA] * scale;
        const float fB = g_demod[b * COUT + coA + 8] * scale;
        const size_t base = ((((size_t)b * COUT + coA) << 6) + y) << 6;
        #pragma unroll
        for (int nf = 0; nf < 4; nf++) {
            const int x = xw + nf * 8 + 2 * tt;
            float2 lo = make_float2(acc[im][nf][0] * fA, acc[im][nf][1] * fA);
            float2 hi = make_float2(acc[im][nf][2] * fB, acc[im][nf][3] * fB);
            *(float2*)(out + base + x) = lo;
            *(float2*)(out + base + (8 << 12) + x) = hi;   // co+8
        }
    }
}

// ---------------------------------------------------------------------------
extern "C" void kernel_launch(void* const* d_in, const int* in_sizes, int n_in,
                              void* d_out, int out_size) {
    const float* input  = (const float*)d_in[0];
    const float* style  = (const float*)d_in[1];
    const float* weight = (const float*)d_in[2];
    const float* mod_w  = (const float*)d_in[3];
    const float* mod_b  = (const float*)d_in[4];
    float* out = (float*)d_out;

    static int smem_set = 0;
    if (!smem_set) {
        cudaFuncSetAttribute(k_conv, cudaFuncAttributeMaxDynamicSharedMemorySize,
                             (SW_WORDS + SIN_WORDS) * 4);
        smem_set = 1;
    }

    k_style<<<dim3(16, 64), 256>>>(style, mod_w, mod_b);
    k_wsq<<<(COUT * CIN + 255) / 256, 256>>>(weight);
    k_wf<<<(4 * 64 * 9 * 1024 + 255) / 256, 256>>>(weight);
    k_demod<<<1024, 256>>>();
    k_conv<<<dim3(4, 32, 16), 256, (SW_WORDS + SIN_WORDS) * 4>>>(input, out);
}

// round 6
// speedup vs baseline: 14.4239x; 2.4983x over previous
#include <cuda_runtime.h>
#include <cuda_fp16.h>
#include <math.h>
#include <stdint.h>

#define B 16
#define CIN 512
#define COUT 512
#define HH 64
#define WW 64
#define SS 512
#define SCALE2 (1.0f / 4608.0f)

// ---------------- scratch (__device__ globals) ----------------
__device__ float g_s[B * CIN];
__device__ float g_demod[B * COUT];
__device__ float g_wsq[COUT * CIN];
// modulated fp16 input, chunk-major, padded halo:
// [b][chunk(32)][yp(66)][xh(66)][ciPair(8)] uint32 (half2 of ci even/odd)
__device__ __align__(16) uint32_t g_inh[(size_t)B * 32 * 66 * 528];
// fp16 weights in per-thread A-fragment order:
// [mt(4)][chunk(32)][tap(9)][wm(2)][mtile(4)][lane(32)][j(4)] uint32 (half2 ci pair)
__device__ __align__(16) uint32_t g_wfA[4 * 32 * 9 * 2 * 4 * 128];

// ---------------- PTX helpers (NO tcgen05 — not supported by build target) --
__device__ __forceinline__ uint32_t smem_u32(const void* p) {
    uint32_t a;
    asm("{ .reg .u64 t; cvta.to.shared.u64 t, %1; cvt.u32.u64 %0, t; }" : "=r"(a) : "l"(p));
    return a;
}
#define MBAR_INIT(a, n) asm volatile("mbarrier.init.shared.b64 [%0], %1;" :: "r"(a), "r"(n) : "memory")
#define MBAR_EXPECT(a, tx) asm volatile("mbarrier.arrive.expect_tx.shared.b64 _, [%0], %1;" :: "r"(a), "r"(tx) : "memory")
#define MBAR_WAIT(a, ph) do {                                                             \
    uint32_t _m = (a), _p = (ph);                                                         \
    asm volatile("{ .reg .pred P; WL%=:\n\t"                                              \
        "mbarrier.try_wait.parity.acquire.cta.shared::cta.b64 P, [%0], %1, 0x989680;\n\t" \
        "@P bra.uni WD%=;\n\t bra.uni WL%=;\n\t WD%=: }" :: "r"(_m), "r"(_p) : "memory"); \
} while (0)
#define FENCE_ASYNC() asm volatile("fence.proxy.async.shared::cta;" ::: "memory")
#define BULK_CP(dst, src, sz, mb)                                                              \
    asm volatile("cp.async.bulk.shared::cta.global.mbarrier::complete_tx::bytes [%0], [%1], %2, [%3];" \
        :: "r"(dst), "l"(src), "r"(sz), "r"(mb) : "memory")
#define MMA_F16(d, a, b0v, b1v)                                                            \
    asm volatile(                                                                          \
        "mma.sync.aligned.m16n8k16.row.col.f32.f16.f16.f32 "                               \
        "{%0,%1,%2,%3}, {%4,%5,%6,%7}, {%8,%9}, {%0,%1,%2,%3};"                            \
        : "+f"(d[0]), "+f"(d[1]), "+f"(d[2]), "+f"(d[3])                                   \
        : "r"(a.x), "r"(a.y), "r"(a.z), "r"(a.w), "r"(b0v), "r"(b1v))

// ---------------- prep kernels ----------------
__global__ void k_style(const float* __restrict__ style, const float* __restrict__ mod_w,
                        const float* __restrict__ mod_b) {
    __shared__ float ss[SS];
    const int b = blockIdx.x, lane = threadIdx.x & 31, warp = threadIdx.x >> 5;
    const int ci = blockIdx.y * 8 + warp;
    for (int i = threadIdx.x; i < SS; i += 256) ss[i] = style[b * SS + i];
    __syncthreads();
    const float* wr = mod_w + (size_t)ci * SS;
    float p = 0.f;
    #pragma unroll 4
    for (int j = lane; j < SS; j += 32) p = fmaf(wr[j], ss[j], p);
    #pragma unroll
    for (int o = 16; o > 0; o >>= 1) p += __shfl_xor_sync(0xffffffffu, p, o);
    if (lane == 0) g_s[b * CIN + ci] = p + mod_b[ci];
}

__global__ void k_wsq(const float* __restrict__ weight) {
    int idx = blockIdx.x * blockDim.x + threadIdx.x;
    if (idx >= COUT * CIN) return;
    const float* w = weight + (size_t)idx * 9;
    float s = 0.f;
    #pragma unroll
    for (int k = 0; k < 9; k++) s = fmaf(w[k], w[k], s);
    g_wsq[idx] = s;
}

__global__ void k_demod() {
    int wid = (blockIdx.x * blockDim.x + threadIdx.x) >> 5;
    int lane = threadIdx.x & 31;
    int b = wid >> 9, co = wid & 511;
    const float* wsq = g_wsq + (size_t)co * CIN;
    const float* sr = g_s + (size_t)b * CIN;
    float p = 0.f;
    #pragma unroll 4
    for (int j = lane; j < CIN; j += 32) { float sv = sr[j]; p = fmaf(wsq[j], sv * sv, p); }
    #pragma unroll
    for (int o = 16; o > 0; o >>= 1) p += __shfl_xor_sync(0xffffffffu, p, o);
    if (lane == 0) g_demod[b * COUT + co] = rsqrtf(SCALE2 * p + 1e-8f);
}

// modulated input -> fp16 chunk-major padded layout (B-operand ready)
__global__ void k_inh(const float* __restrict__ input) {
    __shared__ float sm[16][64];
    const int yp = blockIdx.x;      // 0..65 (padded row; 0 and 65 are zero borders)
    const int chunk = blockIdx.y;   // 0..31
    const int b = blockIdx.z;       // 0..15
    uint32_t* dst = g_inh + (((size_t)(b * 32 + chunk) * 66 + yp) * 528);
    if (yp == 0 || yp == 65) {
        for (int i = threadIdx.x; i < 528; i += 256) dst[i] = 0;
        return;
    }
    const int y = yp - 1;
    const float* sbv = g_s + b * CIN + chunk * 16;
    const float* src = input + ((size_t)b * CIN + chunk * 16) * 4096 + y * 64;
    for (int i = threadIdx.x; i < 1024; i += 256) {
        int ci = i >> 6, x = i & 63;
        sm[ci][x] = src[(size_t)ci * 4096 + x] * __ldg(sbv + ci);
    }
    __syncthreads();
    for (int i = threadIdx.x; i < 528; i += 256) {
        int xh = i >> 3, p = i & 7;
        uint32_t w = 0;
        if (xh >= 1 && xh <= 64) {
            __half2 h = __floats2half2_rn(sm[2 * p][xh - 1], sm[2 * p + 1][xh - 1]);
            w = *(uint32_t*)&h;
        }
        dst[i] = w;
    }
}

// weights -> fp16 A-fragment-major slabs
__global__ void k_wfA(const float* __restrict__ weight) {
    int idx = blockIdx.x * blockDim.x + threadIdx.x;
    if (idx >= 4 * 32 * 9 * 1024) return;
    int j     = idx & 3;
    int lane  = (idx >> 2) & 31;
    int mtile = (idx >> 7) & 3;
    int wm    = (idx >> 9) & 1;
    int t     = (idx >> 10) % 9;
    int rest  = (idx >> 10) / 9;
    int chunk = rest & 31, mt = rest >> 5;
    int g = lane >> 2, tt = lane & 3;
    int co = mt * 128 + wm * 64 + mtile * 16 + g + (j & 1) * 8;
    int ci = chunk * 16 + 2 * tt + (j >> 1) * 8;
    const float* wp = weight + ((size_t)co * CIN + ci) * 9 + t;
    __half2 h = __floats2half2_rn(wp[0], wp[9]);   // (ci, ci+1) at tap t
    g_wfA[idx] = *(uint32_t*)&h;
}

// ---------------- main conv: fp16 mma.sync implicit GEMM, all-bulk staging --
// CTA: 128 co (mt) x 128 px (2 rows x 64 cols), 256 threads, 8 warps 2m x 4n.
// Warp tile 32 co x 32 px; chunk = 16 ci = one k16 slice; 9 taps by smem shift.
#define NCHUNK 32
#define A_SLAB 36864               // 9*2*4*128*4 bytes
#define B_SLAB 8448                // 4 rows * 66 px * 8 words * 4B
#define OFF_A 64
#define OFF_B (OFF_A + 2 * A_SLAB)          // 73792
#define SMEM_TOTAL (OFF_B + 2 * B_SLAB)     // 90688

__global__ void __launch_bounds__(256, 2)
k_conv(float* __restrict__ out) {
    extern __shared__ char smem[];
    const uint32_t sb = smem_u32(smem);
    const int tid = threadIdx.x, lane = tid & 31, wid = tid >> 5;
    const int wm = wid >> 2, wn = wid & 3;
    const int yl = wn >> 1, xw = (wn & 1) * 32;
    const int g = lane >> 2, tt = lane & 3;

    const int mt = blockIdx.x;
    const int y0 = blockIdx.y * 2;
    const int b  = blockIdx.z;

    if (tid == 0) { MBAR_INIT(sb + 0, 1); MBAR_INIT(sb + 8, 1); }
    __syncthreads();

    const uint32_t* gA = g_wfA + (size_t)mt * 32 * 9216;
    const uint32_t* gB = g_inh + (size_t)b * 32 * 66 * 528;

    if (tid == 0) {
        FENCE_ASYNC();
        #pragma unroll
        for (int k = 0; k < 2; k++) {
            uint32_t mb = sb + k * 8;
            MBAR_EXPECT(mb, A_SLAB + B_SLAB);
            BULK_CP(sb + OFF_A + k * A_SLAB, (const void*)(gA + (size_t)k * 9216), A_SLAB, mb);
            BULK_CP(sb + OFF_B + k * B_SLAB, (const void*)(gB + ((size_t)k * 66 + y0) * 528), B_SLAB, mb);
        }
    }

    float acc[4][4][4];
    #pragma unroll
    for (int m = 0; m < 4; m++)
        #pragma unroll
        for (int n = 0; n < 4; n++)
            #pragma unroll
            for (int c = 0; c < 4; c++) acc[m][n][c] = 0.f;

    for (int c = 0; c < NCHUNK; c++) {
        MBAR_WAIT(sb + (c & 1) * 8, (c >> 1) & 1);
        const uint32_t* sA = (const uint32_t*)(smem + OFF_A + (c & 1) * A_SLAB);
        const uint32_t* sB = (const uint32_t*)(smem + OFF_B + (c & 1) * B_SLAB);

        #pragma unroll
        for (int tap = 0; tap < 9; tap++) {
            const int dy = tap / 3, dx = tap % 3;
            const int r = yl + dy;
            const uint32_t* ap = sA + (tap * 2 + wm) * 512 + lane * 4;
            uint4 A0 = *(const uint4*)(ap);
            uint4 A1 = *(const uint4*)(ap + 128);
            uint4 A2 = *(const uint4*)(ap + 256);
            uint4 A3 = *(const uint4*)(ap + 384);
            const uint32_t* bp = sB + (size_t)(r * 66 + xw + dx + g) * 8 + tt;
            #pragma unroll
            for (int nf = 0; nf < 4; nf++) {
                uint32_t b0 = bp[nf * 64];
                uint32_t b1 = bp[nf * 64 + 4];
                MMA_F16(acc[0][nf], A0, b0, b1);
                MMA_F16(acc[1][nf], A1, b0, b1);
                MMA_F16(acc[2][nf], A2, b0, b1);
                MMA_F16(acc[3][nf], A3, b0, b1);
            }
        }
        __syncthreads();
        if (tid == 0 && c + 2 < NCHUNK) {
            const int k = c + 2;
            uint32_t mb = sb + (k & 1) * 8;
            MBAR_EXPECT(mb, A_SLAB + B_SLAB);
            BULK_CP(sb + OFF_A + (k & 1) * A_SLAB, (const void*)(gA + (size_t)k * 9216), A_SLAB, mb);
            BULK_CP(sb + OFF_B + (k & 1) * B_SLAB, (const void*)(gB + ((size_t)k * 66 + y0) * 528), B_SLAB, mb);
        }
    }

    // ---- epilogue: scale * demod, float2 stores ----
    const float scale = rsqrtf(4608.0f);
    const int y = y0 + yl;
    #pragma unroll
    for (int im = 0; im < 4; im++) {
        const int coA = mt * 128 + wm * 64 + im * 16 + g;
        const float fA = g_demod[b * COUT + coA] * scale;
        const float fB = g_demod[b * COUT + coA + 8] * scale;
        const size_t base = ((((size_t)b * COUT + coA) << 6) + y) << 6;
        #pragma unroll
        for (int nf = 0; nf < 4; nf++) {
            const int x = xw + nf * 8 + 2 * tt;
            float2 lo = make_float2(acc[im][nf][0] * fA, acc[im][nf][1] * fA);
            float2 hi = make_float2(acc[im][nf][2] * fB, acc[im][nf][3] * fB);
            *(float2*)(out + base + x) = lo;
            *(float2*)(out + base + ((size_t)8 << 12) + x) = hi;   // co+8 plane
        }
    }
}

// ---------------------------------------------------------------------------
extern "C" void kernel_launch(void* const* d_in, const int* in_sizes, int n_in,
                              void* d_out, int out_size) {
    const float* input  = (const float*)d_in[0];
    const float* style  = (const float*)d_in[1];
    const float* weight = (const float*)d_in[2];
    const float* mod_w  = (const float*)d_in[3];
    const float* mod_b  = (const float*)d_in[4];
    float* out = (float*)d_out;

    static int smem_set = 0;
    if (!smem_set) {
        cudaFuncSetAttribute(k_conv, cudaFuncAttributeMaxDynamicSharedMemorySize, SMEM_TOTAL);
        smem_set = 1;
    }

    k_style<<<dim3(16, 64), 256>>>(style, mod_w, mod_b);
    k_wsq<<<(COUT * CIN + 255) / 256, 256>>>(weight);
    k_wfA<<<(4 * 32 * 9 * 1024 + 255) / 256, 256>>>(weight);
    k_demod<<<1024, 256>>>();
    k_inh<<<dim3(66, 32, 16), 256>>>(input);
    k_conv<<<dim3(4, 32, 16), 256, SMEM_TOTAL>>>(out);
}